// round 3
// baseline (speedup 1.0000x reference)
#include <cuda_runtime.h>

// ---------------------------------------------------------------------------
// KappaGCN forward: two kappa_layers + hyperbolic logits + aggregation.
// Heavy work = 3 GEMMs against A_hat [8192 x 8192]:
//   P1 = A @ [gamma*XW | gamma-1 | 1 | pad]  (40 cols)   (layer 1)
//   P2 = A @ [ ... ]                          (40 cols)   (layer 2)
//   OUT = A @ logits                          (16 cols)
// GEMMs use packed fma.rn.f32x2 (sm_100+) -> 2x fp32 FMA rate.
// Split-K=8 with private partial slices (no atomics), reduced in epilogues.
// ---------------------------------------------------------------------------

#define FULLMASK 0xffffffffu

constexpr int N   = 8192;
constexpr int D   = 32;
constexpr int C   = 16;
constexpr int NC1 = 40;     // padded column count for layer GEMMs (34 real)
constexpr int KSPLIT = 8;
constexpr int BM  = 128;
constexpr int BK  = 32;
constexpr int GT  = 256;    // GEMM threads per block

// ---- scratch (static device arrays; no allocation) ----
__device__ __align__(256) float g_M [N * NC1];              // 1.31 MB
__device__ __align__(256) float g_Pp[KSPLIT * N * NC1];     // 10.5 MB
__device__ __align__(256) float g_X2[N * D];                // 1.05 MB
__device__ __align__(256) float g_L [N * C];                // 0.52 MB
__device__ __align__(256) float g_Po[KSPLIT * N * C];       // 4.2 MB

// ---- helpers ----
__device__ __forceinline__ float wsum(float v) {
#pragma unroll
    for (int o = 16; o > 0; o >>= 1) v += __shfl_xor_sync(FULLMASK, v, o);
    return v;
}

// artanh with reference clipping: clip(x, -1+1e-7, 1-1e-7). float32(1-1e-7)=0.99999988f
__device__ __forceinline__ float artanh_c(float v) {
    v = fminf(fmaxf(v, -0.99999988f), 0.99999988f);
    return atanhf(v);
}

// =============================================================================
// prep: per row i of input X:
//   XW = mobius_matvec(W, x); gamma = 2/max(1-||XW||^2, 1e-15)
//   M[i, 0:32] = gamma*XW;  M[i,32] = gamma-1;  M[i,33] = 1;  M[i,34:40] = 0
// one warp per row, lane = feature dim.
// =============================================================================
__global__ void prep_kernel(const float* __restrict__ X0,
                            const float* __restrict__ W,
                            int useScratch)
{
    __shared__ float Ws[D][D + 1];
    const int tid = threadIdx.x;
    for (int i = tid; i < D * D; i += blockDim.x)
        Ws[i >> 5][i & 31] = W[i];
    __syncthreads();

    const int lane = tid & 31;
    const int row  = blockIdx.x * (blockDim.x >> 5) + (tid >> 5);
    const float* Xin = useScratch ? g_X2 : X0;

    float x  = Xin[row * D + lane];
    float xn = sqrtf(fmaxf(wsum(x * x), 1e-30f));

    float mx = 0.f;
#pragma unroll
    for (int d = 0; d < D; ++d)
        mx = fmaf(__shfl_sync(FULLMASK, x, d), Ws[d][lane], mx);

    float mxn = sqrtf(fmaxf(wsum(mx * mx), 1e-30f));
    float sc  = tanhf(mxn / xn * artanh_c(xn)) / mxn;
    float xw  = sc * mx;
    float xw2 = wsum(xw * xw);
    float gamma = 2.f / fmaxf(1.f - xw2, 1e-15f);

    float* Mrow = g_M + row * NC1;
    Mrow[lane] = gamma * xw;
    if (lane == 0) { Mrow[32] = gamma - 1.f; Mrow[33] = 1.f; }
    if (lane >= 26) Mrow[34 + (lane - 26)] = 0.f;   // zero pad cols 34..39
}

// =============================================================================
// GEMM: P[ks][r][n] = sum_{k in split ks} A[r,k] * M[k,n]
// BM=128 rows x NC cols per block, BK=32, 256 threads, split-K via blockIdx.y.
// Thread computes 2 rows x (NC/8) column-pairs using packed f32x2 FMA.
// =============================================================================
template <int NC>
__global__ void __launch_bounds__(GT) gemm_kernel(const float* __restrict__ A)
{
    static_assert(NC % 8 == 0, "NC must be multiple of 8");
    constexpr int TNP  = NC / 8;             // col-pairs per thread (5 or 2)
    constexpr int MREG = BK * NC / GT;       // staged M floats per thread (5 or 2)

    __shared__ __align__(16) float As[BK][BM + 2];   // pitch 130 (even, low conflict)
    __shared__ __align__(16) float Ms[BK * NC];

    const float* Mg = (NC == NC1) ? g_M  : g_L;
    float*       Pg = (NC == NC1) ? g_Pp : g_Po;

    const int tid  = threadIdx.x;
    const int row0 = blockIdx.x * BM;
    const int kb0  = blockIdx.y * (N / KSPLIT);

    const int rg = tid & 63;        // owns rows 2*rg, 2*rg+1
    const int cp = tid >> 6;        // col-pair phase 0..3

    const int arow = tid >> 3;      // A-tile load: row within 32-row group
    const int ak   = (tid & 7) << 2;// A-tile load: k offset (float4)

    unsigned long long acc[2][TNP];
#pragma unroll
    for (int t = 0; t < 2; ++t)
#pragma unroll
        for (int p = 0; p < TNP; ++p) acc[t][p] = 0ull;

    float4 aReg[4];
    float  mReg[MREG];
    const float4* A4 = reinterpret_cast<const float4*>(A);

    // prologue: stage tile 0
    {
        const int kb = kb0;
#pragma unroll
        for (int i = 0; i < 4; ++i)
            aReg[i] = A4[((size_t)(row0 + arow + i * 32) * N + kb + ak) >> 2];
#pragma unroll
        for (int i = 0; i < MREG; ++i)
            mReg[i] = Mg[kb * NC + i * GT + tid];
    }

    const int iters = (N / KSPLIT) / BK;   // 32
    for (int it = 0; it < iters; ++it) {
        __syncthreads();
        // commit staged tile to smem (A transposed: As[k][row])
#pragma unroll
        for (int i = 0; i < 4; ++i) {
            const int r = arow + i * 32;
            As[ak + 0][r] = aReg[i].x;
            As[ak + 1][r] = aReg[i].y;
            As[ak + 2][r] = aReg[i].z;
            As[ak + 3][r] = aReg[i].w;
        }
#pragma unroll
        for (int i = 0; i < MREG; ++i) Ms[i * GT + tid] = mReg[i];
        __syncthreads();

        // prefetch next tile while computing this one
        if (it + 1 < iters) {
            const int kb = kb0 + (it + 1) * BK;
#pragma unroll
            for (int i = 0; i < 4; ++i)
                aReg[i] = A4[((size_t)(row0 + arow + i * 32) * N + kb + ak) >> 2];
#pragma unroll
            for (int i = 0; i < MREG; ++i)
                mReg[i] = Mg[kb * NC + i * GT + tid];
        }

        // compute: packed-pair FMAs
#pragma unroll
        for (int k = 0; k < BK; ++k) {
            unsigned long long a2 =
                *reinterpret_cast<const unsigned long long*>(&As[k][2 * rg]);
            unsigned int alo, ahi;
            asm("mov.b64 {%0,%1}, %2;" : "=r"(alo), "=r"(ahi) : "l"(a2));
            unsigned long long aa0, aa1;
            asm("mov.b64 %0, {%1,%1};" : "=l"(aa0) : "r"(alo));
            asm("mov.b64 %0, {%1,%1};" : "=l"(aa1) : "r"(ahi));
#pragma unroll
            for (int p = 0; p < TNP; ++p) {
                unsigned long long mm =
                    *reinterpret_cast<const unsigned long long*>(
                        &Ms[k * NC + 2 * (cp + 4 * p)]);
                asm("fma.rn.f32x2 %0, %1, %2, %0;" : "+l"(acc[0][p]) : "l"(aa0), "l"(mm));
                asm("fma.rn.f32x2 %0, %1, %2, %0;" : "+l"(acc[1][p]) : "l"(aa1), "l"(mm));
            }
        }
    }

    // epilogue: write this split's partial (8B stores, aligned: NC even)
    float* dst0 = Pg + (size_t)blockIdx.y * N * NC;
#pragma unroll
    for (int t = 0; t < 2; ++t) {
        const int row = row0 + 2 * rg + t;
#pragma unroll
        for (int p = 0; p < TNP; ++p)
            *reinterpret_cast<unsigned long long*>(
                dst0 + (size_t)row * NC + 2 * (cp + 4 * p)) = acc[t][p];
    }
}

// =============================================================================
// post: reduce split-K partials, then
//   denom clamp, a_mean = msm(0.5, nom/denom), AXW = msm(alpha, a_mean),
//   X_out = expmap0(relu(logmap0(AXW))).  One warp per row.
// =============================================================================
__global__ void post_kernel()
{
    const int tid  = threadIdx.x;
    const int lane = tid & 31;
    const int row  = blockIdx.x * (blockDim.x >> 5) + (tid >> 5);

    float nom = 0.f, den = 0.f, alp = 0.f;
#pragma unroll
    for (int s = 0; s < KSPLIT; ++s) {
        const float* pr = g_Pp + ((size_t)s * N + row) * NC1;
        nom += pr[lane];
        den += pr[32];
        alp += pr[33];
    }
    den = (den >= 0.f) ? fmaxf(den, 1e-10f) : fminf(den, -1e-10f);

    float v  = nom / den;
    float vn = sqrtf(fmaxf(wsum(v * v), 1e-30f));

    // a_mean = tanh(0.5*artanh(vn)) * v/vn
    float t  = tanhf(0.5f * artanh_c(vn));
    float am = t * (v / vn);
    float amn = sqrtf(fmaxf(wsum(am * am), 1e-30f));

    // AXW = tanh(alpha*artanh(||a_mean||)) * a_mean/||a_mean||
    float u   = tanhf(alp * artanh_c(amn));
    float axw = u * (am / amn);
    float axwn = sqrtf(fmaxf(wsum(axw * axw), 1e-30f));

    // logmap0 -> relu -> expmap0
    float l  = artanh_c(axwn) * (axw / axwn);
    float r  = fmaxf(l, 0.f);
    float rn = sqrtf(fmaxf(wsum(r * r), 1e-30f));
    g_X2[row * D + lane] = tanhf(rn) * (r / rn);
}

// =============================================================================
// logits: hyperbolic MLR logits per (row, class). One warp per row.
// =============================================================================
__global__ void logits_kernel(const float* __restrict__ Wl,   // [D][C]
                              const float* __restrict__ pks)  // [C][D]
{
    __shared__ float bs[C][D];
    __shared__ float ws[C][D];          // ws[c][d] = Wl[d][c]
    __shared__ float an_s[C], lam_s[C], b2_s[C];

    const int tid = threadIdx.x;
    for (int i = tid; i < C * D; i += blockDim.x) {
        const int c = i >> 5, d = i & 31;
        bs[c][d] = pks[i];
        ws[c][d] = Wl[d * C + c];
    }
    __syncthreads();
    if (tid < C) {
        float s2 = 0.f, b2 = 0.f;
        for (int d = 0; d < D; ++d) {
            s2 += ws[tid][d] * ws[tid][d];
            b2 += bs[tid][d] * bs[tid][d];
        }
        an_s[tid]  = fmaxf(sqrtf(s2), 1e-10f);
        b2_s[tid]  = b2;
        lam_s[tid] = 2.f / fmaxf(1.f - b2, 1e-15f);
    }
    __syncthreads();

    const int lane = tid & 31;
    const int row  = blockIdx.x * (blockDim.x >> 5) + (tid >> 5);

    float x  = g_X2[row * D + lane];
    float y2 = wsum(x * x);

    float myLogit = 0.f;
#pragma unroll 1
    for (int c = 0; c < C; ++c) {
        float bd  = bs[c][lane];
        float bx  = wsum(bd * x);
        float b2  = b2_s[c];
        float c1  = 1.f - 2.f * bx + y2;     // (1 - 2K xy - K y2) with x = -b
        float c2  = 1.f - b2;                // (1 + K x2)
        float dd  = fmaxf(1.f - 2.f * bx + b2 * y2, 1e-15f);
        float z   = (c2 * x - c1 * bd) / dd;
        float za  = wsum(z * ws[c][lane]);
        float zn  = fmaxf(sqrtf(fmaxf(wsum(z * z), 1e-30f)), 1e-10f);
        float an  = an_s[c];
        float dist = asinhf(2.f * za / ((1.f - zn * zn) * an));
        float lg  = lam_s[c] * an * dist;
        if (lane == c) myLogit = lg;
    }
    if (lane < C) g_L[row * C + lane] = myLogit;
}

// =============================================================================
// reduce split-K partials of the final A @ logits into d_out
// =============================================================================
__global__ void reduce_kernel(float* __restrict__ out)
{
    const int i = blockIdx.x * blockDim.x + threadIdx.x;  // < N*C
    float s = 0.f;
#pragma unroll
    for (int k = 0; k < KSPLIT; ++k) s += g_Po[(size_t)k * N * C + i];
    out[i] = s;
}

// =============================================================================
// launch
// =============================================================================
extern "C" void kernel_launch(void* const* d_in, const int* in_sizes, int n_in,
                              void* d_out, int out_size)
{
    const float* X  = (const float*)d_in[0];   // [N, D]
    const float* A  = (const float*)d_in[1];   // [N, N]
    const float* W1 = (const float*)d_in[2];   // [D, D]
    const float* W2 = (const float*)d_in[3];   // [D, D]
    const float* Wl = (const float*)d_in[4];   // [D, C]
    const float* pk = (const float*)d_in[5];   // [C, D]

    const dim3 ggrid(N / BM, KSPLIT);          // (64, 8)
    const int  rgrid = N / (256 / 32);         // 1024 blocks, warp-per-row

    // layer 1
    prep_kernel<<<rgrid, 256>>>(X, W1, 0);
    gemm_kernel<NC1><<<ggrid, GT>>>(A);
    post_kernel<<<rgrid, 256>>>();

    // layer 2
    prep_kernel<<<rgrid, 256>>>(X, W2, 1);
    gemm_kernel<NC1><<<ggrid, GT>>>(A);
    post_kernel<<<rgrid, 256>>>();

    // logits + aggregation
    logits_kernel<<<rgrid, 256>>>(Wl, pk);
    gemm_kernel<C><<<ggrid, GT>>>(A);
    reduce_kernel<<<(N * C) / 256, 256>>>((float*)d_out);
}